// round 14
// baseline (speedup 1.0000x reference)
#include <cuda_runtime.h>
#include <cuda_bf16.h>
#include <math.h>
#include <stdint.h>

#define BSZ 4
#define NL  512
#define DM  1024
#define NH  16
#define HD  64

// ---------------- scratch (static device globals; no allocation) ----------------
__device__ float g_s[BSZ*NL*NL];           // s[b,i,j] accumulated over heads  4 MB
__device__ float g_u[BSZ*NH*NL];           // u[b,h,j]
__device__ float g_wvo[NH*DM];             // wvo[h][din]
__device__ float g_bvo[NH];
// split-bf16 operands
__device__ __nv_bfloat16 g_xhi[BSZ*NL*DM];     // x hi  [m][k]
__device__ __nv_bfloat16 g_xlo[BSZ*NL*DM];     // x lo
__device__ __nv_bfloat16 g_wthi[2*DM*DM];      // W^T hi [which][n][k]
__device__ __nv_bfloat16 g_wtlo[2*DM*DM];      // W^T lo
__device__ __nv_bfloat16 g_qhi[BSZ*NH*NL*HD];  // q/8 hi [b,h,i,d]
__device__ __nv_bfloat16 g_qlo[BSZ*NH*NL*HD];
__device__ __nv_bfloat16 g_khi[BSZ*NH*NL*HD];  // k hi   [b,h,j,d]
__device__ __nv_bfloat16 g_klo[BSZ*NH*NL*HD];

// ============================ HMMA helpers (arch-portable PTX) ============================
__device__ __forceinline__ uint32_t smem_u32(const void* p) {
    uint32_t a;
    asm("{ .reg .u64 t; cvta.to.shared.u64 t, %1; cvt.u32.u64 %0, t; }" : "=r"(a) : "l"(p));
    return a;
}
__device__ __forceinline__ void ldsm_x4(uint32_t& r0, uint32_t& r1, uint32_t& r2, uint32_t& r3,
                                        uint32_t addr) {
    asm volatile("ldmatrix.sync.aligned.m8n8.x4.shared.b16 {%0,%1,%2,%3}, [%4];"
                 : "=r"(r0), "=r"(r1), "=r"(r2), "=r"(r3) : "r"(addr));
}
__device__ __forceinline__ void ldsm_x2(uint32_t& r0, uint32_t& r1, uint32_t addr) {
    asm volatile("ldmatrix.sync.aligned.m8n8.x2.shared.b16 {%0,%1}, [%2];"
                 : "=r"(r0), "=r"(r1) : "r"(addr));
}
__device__ __forceinline__ void mma_bf16(float* d, const uint32_t* a, const uint32_t* b) {
    asm volatile("mma.sync.aligned.m16n8k16.row.col.f32.bf16.bf16.f32 "
                 "{%0,%1,%2,%3}, {%4,%5,%6,%7}, {%8,%9}, {%0,%1,%2,%3};"
                 : "+f"(d[0]), "+f"(d[1]), "+f"(d[2]), "+f"(d[3])
                 : "r"(a[0]), "r"(a[1]), "r"(a[2]), "r"(a[3]), "r"(b[0]), "r"(b[1]));
}
__device__ __forceinline__ void split_bf16(float v, __nv_bfloat16& hi, __nv_bfloat16& lo) {
    hi = __float2bfloat16(v);
    lo = __float2bfloat16(v - __bfloat162float(hi));
}

// ---------------- prep: zero g_s (graph-safe) ----------------
__global__ void __launch_bounds__(256) k_zero_s() {
    int t = blockIdx.x * 256 + threadIdx.x;
    ((float4*)g_s)[t] = make_float4(0.f, 0.f, 0.f, 0.f);
}

// ---------------- prep: split x into bf16 hi/lo ----------------
__global__ void __launch_bounds__(256) k_split_x(const float* __restrict__ x) {
    int t = blockIdx.x * 256 + threadIdx.x;
    float4 v = ((const float4*)x)[t];
    float vv[4] = {v.x, v.y, v.z, v.w};
    __nv_bfloat16 hi[4], lo[4];
    #pragma unroll
    for (int i = 0; i < 4; i++) split_bf16(vv[i], hi[i], lo[i]);
    __nv_bfloat162* ph = (__nv_bfloat162*)g_xhi;
    __nv_bfloat162* pl = (__nv_bfloat162*)g_xlo;
    ph[t*2]   = __nv_bfloat162(hi[0], hi[1]);
    ph[t*2+1] = __nv_bfloat162(hi[2], hi[3]);
    pl[t*2]   = __nv_bfloat162(lo[0], lo[1]);
    pl[t*2+1] = __nv_bfloat162(lo[2], lo[3]);
}

// ---------------- prep: transpose + split wq/wk -> W^T hi/lo ----------------
__global__ void __launch_bounds__(256) k_split_w(const float* __restrict__ wq,
                                                 const float* __restrict__ wk) {
    __shared__ float tile[32][33];
    int which = blockIdx.z;
    const float* src = which ? wk : wq;            // src[k][n]
    int k0 = blockIdx.y * 32, n0 = blockIdx.x * 32;
    int tx = threadIdx.x & 31, ty = threadIdx.x >> 5;
    #pragma unroll
    for (int i = 0; i < 4; i++)
        tile[ty + 8*i][tx] = src[(size_t)(k0 + ty + 8*i) * DM + n0 + tx];
    __syncthreads();
    size_t base = (size_t)which * DM * DM;
    #pragma unroll
    for (int i = 0; i < 4; i++) {
        float v = tile[tx][ty + 8*i];
        __nv_bfloat16 hi, lo;
        split_bf16(v, hi, lo);
        size_t idx = base + (size_t)(n0 + ty + 8*i) * DM + k0 + tx;
        g_wthi[idx] = hi;
        g_wtlo[idx] = lo;
    }
}

// ---------------- kernel C: Q/K projection via mma.sync -> split-bf16 q/k ----------
#define PITCH   40
#define T_BYTES (128 * PITCH * 2)
#define OA_HI   0
#define OA_LO   (T_BYTES)
#define OB_HI   (2 * T_BYTES)
#define OB_LO   (3 * T_BYTES)
#define BUF_B   (4 * T_BYTES)
#define HMMA_SMEM (2 * BUF_B)
__global__ void __launch_bounds__(256) k_proj_hmma(const float* __restrict__ bq,
                                                   const float* __restrict__ bk) {
    extern __shared__ char smem[];
    uint32_t sb = smem_u32(smem);
    int tid = threadIdx.x, lane = tid & 31, wid = tid >> 5;
    int which = blockIdx.z;
    const __nv_bfloat16* Bh = g_wthi + (size_t)which * DM * DM;
    const __nv_bfloat16* Bl = g_wtlo + (size_t)which * DM * DM;
    __nv_bfloat16* ohi = which ? g_khi : g_qhi;
    __nv_bfloat16* olo = which ? g_klo : g_qlo;
    const float* bvec = which ? bk : bq;
    const float oscale = which ? 1.0f : 0.125f;    // fold 1/sqrt(64) into q
    int m0 = blockIdx.y * 128, n0 = blockIdx.x * 128;
    int warp_m = wid & 1, warp_n = wid >> 1;
    int wm_base = warp_m * 64, wn_base = warp_n * 32;

    float acc[4][4][4];
    #pragma unroll
    for (int mi = 0; mi < 4; mi++)
        #pragma unroll
        for (int ni = 0; ni < 4; ni++)
            #pragma unroll
            for (int e = 0; e < 4; e++) acc[mi][ni][e] = 0.f;

    int l_row[2], l_c8[2];
    #pragma unroll
    for (int t = 0; t < 2; t++) { int f = tid + t * 256; l_row[t] = f >> 2; l_c8[t] = f & 3; }

    uint4 rah[2], ral[2], rbh[2], rbl[2];
    auto load_regs = [&](int c) {
        int k0 = c * 32;
        #pragma unroll
        for (int t = 0; t < 2; t++) {
            size_t ga = (size_t)(m0 + l_row[t]) * DM + k0 + l_c8[t] * 8;
            size_t gb = (size_t)(n0 + l_row[t]) * DM + k0 + l_c8[t] * 8;
            rah[t] = *(const uint4*)(g_xhi + ga);
            ral[t] = *(const uint4*)(g_xlo + ga);
            rbh[t] = *(const uint4*)(Bh + gb);
            rbl[t] = *(const uint4*)(Bl + gb);
        }
    };
    auto store_smem = [&](int buf) {
        char* base = smem + buf * BUF_B;
        #pragma unroll
        for (int t = 0; t < 2; t++) {
            uint32_t off = (uint32_t)(l_row[t] * (PITCH * 2) + l_c8[t] * 16);
            *(uint4*)(base + OA_HI + off) = rah[t];
            *(uint4*)(base + OA_LO + off) = ral[t];
            *(uint4*)(base + OB_HI + off) = rbh[t];
            *(uint4*)(base + OB_LO + off) = rbl[t];
        }
    };

    load_regs(0);
    store_smem(0);
    __syncthreads();

    int buf = 0;
    for (int c = 0; c < 32; c++) {
        if (c < 31) load_regs(c + 1);
        uint32_t bb = sb + buf * BUF_B;
        #pragma unroll
        for (int ks = 0; ks < 2; ks++) {
            uint32_t ah[4][4], al[4][4], bh[4][2], bl[4][2];
            #pragma unroll
            for (int mi = 0; mi < 4; mi++) {
                uint32_t ro = (uint32_t)((wm_base + mi * 16 + (lane & 15)) * (PITCH * 2)
                              + (lane >> 4) * 16 + ks * 32);
                ldsm_x4(ah[mi][0], ah[mi][1], ah[mi][2], ah[mi][3], bb + OA_HI + ro);
                ldsm_x4(al[mi][0], al[mi][1], al[mi][2], al[mi][3], bb + OA_LO + ro);
            }
            #pragma unroll
            for (int ni = 0; ni < 4; ni++) {
                uint32_t ro = (uint32_t)((wn_base + ni * 8 + (lane & 7)) * (PITCH * 2)
                              + ((lane >> 3) & 1) * 16 + ks * 32);
                ldsm_x2(bh[ni][0], bh[ni][1], bb + OB_HI + ro);
                ldsm_x2(bl[ni][0], bl[ni][1], bb + OB_LO + ro);
            }
            #pragma unroll
            for (int mi = 0; mi < 4; mi++)
                #pragma unroll
                for (int ni = 0; ni < 4; ni++) {
                    mma_bf16(acc[mi][ni], ah[mi], bh[ni]);
                    mma_bf16(acc[mi][ni], ah[mi], bl[ni]);
                    mma_bf16(acc[mi][ni], al[mi], bh[ni]);
                }
        }
        if (c < 31) {
            store_smem(buf ^ 1);
            __syncthreads();
            buf ^= 1;
        }
    }

    int groupID = lane >> 2, qc = (lane & 3) * 2;
    #pragma unroll
    for (int mi = 0; mi < 4; mi++) {
        #pragma unroll
        for (int half = 0; half < 2; half++) {
            int m = m0 + wm_base + mi * 16 + groupID + half * 8;
            int b = m >> 9, ii = m & (NL - 1);
            #pragma unroll
            for (int ni = 0; ni < 4; ni++) {
                int n = n0 + wn_base + ni * 8 + qc;
                int h = n >> 6, d = n & 63;
                float vx = (acc[mi][ni][half * 2 + 0] + bvec[n])     * oscale;
                float vy = (acc[mi][ni][half * 2 + 1] + bvec[n + 1]) * oscale;
                __nv_bfloat16 hx, lx, hy, ly;
                split_bf16(vx, hx, lx);
                split_bf16(vy, hy, ly);
                size_t o = ((size_t)(b * NH + h) * NL + ii) * HD + d;
                *(__nv_bfloat162*)(ohi + o) = __nv_bfloat162(hx, hy);
                *(__nv_bfloat162*)(olo + o) = __nv_bfloat162(lx, ly);
            }
        }
    }
}

// ---------------- kernel A: fold wo into wv -> wvo (1024x16) ----------------
__global__ void __launch_bounds__(256) k_wvo(const float* __restrict__ wv,
                                             const float* __restrict__ wo,
                                             const float* __restrict__ bv) {
    int h = blockIdx.x;
    int din = blockIdx.y * 256 + threadIdx.x;
    const float* wvrow = wv + (size_t)din * DM + h * HD;
    const float* worow = wo + h * HD;
    float acc = 0.f;
    #pragma unroll
    for (int e = 0; e < HD; e++) acc += wvrow[e] * worow[e];
    g_wvo[h * DM + din] = acc;
    if (din == 0) {
        float bb = 0.f;
        #pragma unroll
        for (int e = 0; e < HD; e++) bb += bv[h * HD + e] * worow[e];
        g_bvo[h] = bb;
    }
}

// ---------------- kernel B: u = X @ wvo^T; 8 x-rows staged in smem, wvo in regs ----
__global__ void __launch_bounds__(512) k_u(const float* __restrict__ x) {
    __shared__ float xs[8 * DM];               // 32 KB
    int tid = threadIdx.x, lane = tid & 31, h = tid >> 5;   // warp = head
    int row0 = blockIdx.x * 8;                 // 256 blocks
    const float4* src = (const float4*)(x + (size_t)row0 * DM);
    #pragma unroll
    for (int t = 0; t < 4; t++)
        ((float4*)xs)[tid + t * 512] = src[tid + t * 512];
    float4 wr[8];
    const float4* wv4 = (const float4*)(g_wvo + h * DM);
    #pragma unroll
    for (int t = 0; t < 8; t++) wr[t] = wv4[lane + 32 * t];
    float bvo = g_bvo[h];
    __syncthreads();
    #pragma unroll
    for (int rr = 0; rr < 8; rr++) {
        const float4* xr4 = (const float4*)(xs + rr * DM);
        float acc = 0.f;
        #pragma unroll
        for (int t = 0; t < 8; t++) {
            float4 xv = xr4[lane + 32 * t];
            acc += xv.x * wr[t].x + xv.y * wr[t].y + xv.z * wr[t].z + xv.w * wr[t].w;
        }
        #pragma unroll
        for (int o = 16; o > 0; o >>= 1) acc += __shfl_xor_sync(0xffffffffu, acc, o);
        if (lane == 0) {
            int m = row0 + rr;
            int b = m >> 9, j = m & (NL - 1);
            g_u[(b * NH + h) * NL + j] = acc + bvo;
        }
    }
}

// ---------------- kernel D: HMMA logits -> exp -> e-tile in smem -> s atomics ----
// block = (b, h, 64-row i-tile); e kept in smem; irs applied at block end.
#define QP2   144                          // 72 bf16 row pitch
#define AQ_HI 0
#define AQ_LO 9216
#define AK_HI 18432
#define AK_LO 36864
#define AE    55296                        // 64*512 fp32 = 131072 B
#define ARS   186368                       // 4*64 fp32
#define AIRS  187392                       // 64 fp32
#define ATTN_SMEM 187648
__global__ void __launch_bounds__(256) k_attn(const float* __restrict__ bias,
                                              const int* __restrict__ mask) {
    extern __shared__ char smem[];
    uint32_t sb = smem_u32(smem);
    float* e_sm   = (float*)(smem + AE);
    float* rs_sm  = (float*)(smem + ARS);
    float* irs_sm = (float*)(smem + AIRS);
    int tid = threadIdx.x, lane = tid & 31, wid = tid >> 5;
    int warp_m = wid & 1, warp_n = wid >> 1;
    int wm = warp_m * 32, wn = warp_n * 32;
    int b = blockIdx.z, h = blockIdx.y, i0 = blockIdx.x * 64;
    const __nv_bfloat16* qh = g_qhi + ((size_t)(b * NH + h) * NL + i0) * HD;
    const __nv_bfloat16* ql = g_qlo + ((size_t)(b * NH + h) * NL + i0) * HD;
    const __nv_bfloat16* kh = g_khi + (size_t)(b * NH + h) * NL * HD;
    const __nv_bfloat16* kl = g_klo + (size_t)(b * NH + h) * NL * HD;
    const float* urow = g_u + (size_t)(b * NH + h) * NL;

    // q tile: 64 rows x 8 chunks
    #pragma unroll
    for (int t = 0; t < 2; t++) {
        int f = tid + t * 256;
        int rr = f >> 3, c = f & 7;
        *(uint4*)(smem + AQ_HI + rr * QP2 + c * 16) = *(const uint4*)(qh + rr * HD + c * 8);
        *(uint4*)(smem + AQ_LO + rr * QP2 + c * 16) = *(const uint4*)(ql + rr * HD + c * 8);
    }
    int groupID = lane >> 2, qc = (lane & 3) * 2;
    float rs4[4] = {0.f, 0.f, 0.f, 0.f};

    for (int jt = 0; jt < NL; jt += 128) {
        __syncthreads();
        #pragma unroll
        for (int t = 0; t < 4; t++) {
            int f = tid + t * 256;
            int rr = f >> 3, c = f & 7;
            *(uint4*)(smem + AK_HI + rr * QP2 + c * 16) =
                *(const uint4*)(kh + (size_t)(jt + rr) * HD + c * 8);
            *(uint4*)(smem + AK_LO + rr * QP2 + c * 16) =
                *(const uint4*)(kl + (size_t)(jt + rr) * HD + c * 8);
        }
        __syncthreads();

        float acc[2][4][4];
        #pragma unroll
        for (int mi = 0; mi < 2; mi++)
            #pragma unroll
            for (int ni = 0; ni < 4; ni++)
                #pragma unroll
                for (int e = 0; e < 4; e++) acc[mi][ni][e] = 0.f;

        #pragma unroll
        for (int ks = 0; ks < 4; ks++) {
            uint32_t ah[2][4], al[2][4], bh[4][2], bl[4][2];
            #pragma unroll
            for (int mi = 0; mi < 2; mi++) {
                uint32_t ro = (uint32_t)((wm + mi * 16 + (lane & 15)) * QP2
                              + (lane >> 4) * 16 + ks * 32);
                ldsm_x4(ah[mi][0], ah[mi][1], ah[mi][2], ah[mi][3], sb + AQ_HI + ro);
                ldsm_x4(al[mi][0], al[mi][1], al[mi][2], al[mi][3], sb + AQ_LO + ro);
            }
            #pragma unroll
            for (int ni = 0; ni < 4; ni++) {
                uint32_t ro = (uint32_t)((wn + ni * 8 + (lane & 7)) * QP2
                              + ((lane >> 3) & 1) * 16 + ks * 32);
                ldsm_x2(bh[ni][0], bh[ni][1], sb + AK_HI + ro);
                ldsm_x2(bl[ni][0], bl[ni][1], sb + AK_LO + ro);
            }
            #pragma unroll
            for (int mi = 0; mi < 2; mi++)
                #pragma unroll
                for (int ni = 0; ni < 4; ni++) {
                    mma_bf16(acc[mi][ni], ah[mi], bh[ni]);
                    mma_bf16(acc[mi][ni], ah[mi], bl[ni]);
                    mma_bf16(acc[mi][ni], al[mi], bh[ni]);
                }
        }

        float2 uv2[4];
        #pragma unroll
        for (int ni = 0; ni < 4; ni++)
            uv2[ni] = *(const float2*)&urow[jt + wn + ni * 8 + qc];
        #pragma unroll
        for (int mi = 0; mi < 2; mi++) {
            #pragma unroll
            for (int half = 0; half < 2; half++) {
                int gl = wm + mi * 16 + groupID + half * 8;
                int gi = i0 + gl;
                const float* brow = bias + ((size_t)(b * NH + h) * NL + gi) * NL + jt;
                const int*   mrow = mask + ((size_t)b * NL + gi) * NL + jt;
                float rloc = 0.f;
                #pragma unroll
                for (int ni = 0; ni < 4; ni++) {
                    int col = wn + ni * 8 + qc;
                    float2 bb = *(const float2*)&brow[col];
                    int2   mm = *(const int2*)&mrow[col];
                    float e0 = mm.x ? __expf(acc[mi][ni][half * 2 + 0] + bb.x) : 0.f;
                    float e1 = mm.y ? __expf(acc[mi][ni][half * 2 + 1] + bb.y) : 0.f;
                    rloc += e0 + e1;
                    *(float2*)&e_sm[gl * NL + jt + col] =
                        make_float2(e0 * uv2[ni].x, e1 * uv2[ni].y);
                }
                rs4[mi * 2 + half] += rloc;
            }
        }
    }

    // row sums: quad-lane reduce, deposit per warp_n, combine, invert
    #pragma unroll
    for (int i = 0; i < 4; i++) {
        rs4[i] += __shfl_xor_sync(0xffffffffu, rs4[i], 1);
        rs4[i] += __shfl_xor_sync(0xffffffffu, rs4[i], 2);
    }
    if ((lane & 3) == 0) {
        #pragma unroll
        for (int mi = 0; mi < 2; mi++)
            #pragma unroll
            for (int half = 0; half < 2; half++)
                rs_sm[warp_n * 64 + wm + mi * 16 + groupID + half * 8] = rs4[mi * 2 + half];
    }
    __syncthreads();
    if (tid < 64) {
        float s = rs_sm[tid] + rs_sm[64 + tid] + rs_sm[128 + tid] + rs_sm[192 + tid];
        irs_sm[tid] = 1.f / s;
    }
    __syncthreads();

    // scatter: s[b, i0+i, j] += irs[i] * e[i][j]
    float* gs = g_s + ((size_t)b * NL + i0) * NL;
    const float4* e4 = (const float4*)e_sm;
    for (int idx = tid; idx < 64 * 128; idx += 256) {
        int i = idx >> 7, j4 = (idx & 127) * 4;
        float4 ev = e4[idx];
        float ir = irs_sm[i];
        float* dst = gs + (size_t)i * NL + j4;
        atomicAdd(dst + 0, ev.x * ir);
        atomicAdd(dst + 1, ev.y * ir);
        atomicAdd(dst + 2, ev.z * ir);
        atomicAdd(dst + 3, ev.w * ir);
    }
}

// ---------------- kernel E: force[c] = r[b,c,i,:] . s[b,i,:] + bo ----------
__global__ void __launch_bounds__(128) k_out(const float* __restrict__ r,
                                             const float* __restrict__ bo,
                                             float* __restrict__ out) {
    int bi = blockIdx.x;
    int b = bi >> 9, i = bi & (NL - 1);
    __shared__ float red[3][4];
    int tid = threadIdx.x, lane = tid & 31, wrp = tid >> 5;
    float4 sv = ((const float4*)(g_s + ((size_t)b * NL + i) * NL))[tid];
    float p[3];
    #pragma unroll
    for (int c = 0; c < 3; c++) {
        float4 rv = ((const float4*)(r + ((size_t)(b * 3 + c) * NL + i) * NL))[tid];
        p[c] = rv.x * sv.x + rv.y * sv.y + rv.z * sv.z + rv.w * sv.w;
    }
    #pragma unroll
    for (int c = 0; c < 3; c++) {
        #pragma unroll
        for (int o = 16; o > 0; o >>= 1)
            p[c] += __shfl_xor_sync(0xffffffffu, p[c], o);
        if (lane == 0) red[c][wrp] = p[c];
    }
    __syncthreads();
    if (tid < 3)
        out[bi * 3 + tid] = red[tid][0] + red[tid][1] + red[tid][2] + red[tid][3] + bo[0];
}

// ---------------- launch ----------------
extern "C" void kernel_launch(void* const* d_in, const int* in_sizes, int n_in,
                              void* d_out, int out_size) {
    const float* x    = (const float*)d_in[0];
    const float* r    = (const float*)d_in[1];
    const float* bias = (const float*)d_in[2];
    const int*   mask = (const int*)d_in[3];
    const float* wq   = (const float*)d_in[4];
    const float* bq   = (const float*)d_in[5];
    const float* wk   = (const float*)d_in[6];
    const float* bk   = (const float*)d_in[7];
    const float* wv   = (const float*)d_in[8];
    const float* bv   = (const float*)d_in[9];
    const float* wo   = (const float*)d_in[10];
    const float* bo   = (const float*)d_in[11];
    float* out = (float*)d_out;

    cudaFuncSetAttribute(k_attn, cudaFuncAttributeMaxDynamicSharedMemorySize, ATTN_SMEM);
    cudaFuncSetAttribute(k_proj_hmma, cudaFuncAttributeMaxDynamicSharedMemorySize, HMMA_SMEM);

    k_zero_s<<<BSZ * NL * NL / 1024, 256>>>();
    k_split_x<<<BSZ * NL * DM / 1024, 256>>>(x);
    k_split_w<<<dim3(DM / 32, DM / 32, 2), 256>>>(wq, wk);
    k_wvo<<<dim3(NH, 4), 256>>>(wv, wo, bv);
    k_u<<<BSZ * NL / 8, 512>>>(x);
    k_proj_hmma<<<dim3(DM / 128, (BSZ * NL) / 128, 2), 256, HMMA_SMEM>>>(bq, bk);
    k_attn<<<dim3(NL / 64, NH, BSZ), 256, ATTN_SMEM>>>(bias, mask);
    k_out<<<BSZ * NL, 128>>>(r, bo, out);
}

// round 15
// speedup vs baseline: 1.3920x; 1.3920x over previous
#include <cuda_runtime.h>
#include <cuda_bf16.h>
#include <math.h>
#include <stdint.h>

#define BSZ 4
#define NL  512
#define DM  1024
#define NH  16
#define HD  64

// ---------------- scratch (static device globals; no allocation) ----------------
__device__ float g_w[BSZ*NH*NL*NL];        // ew[b,h,i,j] = exp(logit)*u[h,j]  64 MB
__device__ float g_irs[BSZ*NH*NL];         // 1/rowsum[b,h,i]
__device__ float g_u[BSZ*NH*NL];           // u[b,h,j]
__device__ float g_wvo[NH*DM];             // wvo[h][din]
__device__ float g_bvo[NH];
// split-bf16 operands
__device__ __nv_bfloat16 g_xhi[BSZ*NL*DM];     // x hi  [m][k]
__device__ __nv_bfloat16 g_xlo[BSZ*NL*DM];     // x lo
__device__ __nv_bfloat16 g_wthi[2*DM*DM];      // W^T hi [which][n][k]
__device__ __nv_bfloat16 g_wtlo[2*DM*DM];      // W^T lo
__device__ __nv_bfloat16 g_qhi[BSZ*NH*NL*HD];  // q/8 hi [b,h,i,d]
__device__ __nv_bfloat16 g_qlo[BSZ*NH*NL*HD];
__device__ __nv_bfloat16 g_khi[BSZ*NH*NL*HD];  // k hi   [b,h,j,d]
__device__ __nv_bfloat16 g_klo[BSZ*NH*NL*HD];

// ============================ HMMA helpers (arch-portable PTX) ============================
__device__ __forceinline__ uint32_t smem_u32(const void* p) {
    uint32_t a;
    asm("{ .reg .u64 t; cvta.to.shared.u64 t, %1; cvt.u32.u64 %0, t; }" : "=r"(a) : "l"(p));
    return a;
}
__device__ __forceinline__ void ldsm_x4(uint32_t& r0, uint32_t& r1, uint32_t& r2, uint32_t& r3,
                                        uint32_t addr) {
    asm volatile("ldmatrix.sync.aligned.m8n8.x4.shared.b16 {%0,%1,%2,%3}, [%4];"
                 : "=r"(r0), "=r"(r1), "=r"(r2), "=r"(r3) : "r"(addr));
}
__device__ __forceinline__ void ldsm_x2(uint32_t& r0, uint32_t& r1, uint32_t addr) {
    asm volatile("ldmatrix.sync.aligned.m8n8.x2.shared.b16 {%0,%1}, [%2];"
                 : "=r"(r0), "=r"(r1) : "r"(addr));
}
__device__ __forceinline__ void mma_bf16(float* d, const uint32_t* a, const uint32_t* b) {
    asm volatile("mma.sync.aligned.m16n8k16.row.col.f32.bf16.bf16.f32 "
                 "{%0,%1,%2,%3}, {%4,%5,%6,%7}, {%8,%9}, {%0,%1,%2,%3};"
                 : "+f"(d[0]), "+f"(d[1]), "+f"(d[2]), "+f"(d[3])
                 : "r"(a[0]), "r"(a[1]), "r"(a[2]), "r"(a[3]), "r"(b[0]), "r"(b[1]));
}
__device__ __forceinline__ void split_bf16(float v, __nv_bfloat16& hi, __nv_bfloat16& lo) {
    hi = __float2bfloat16(v);
    lo = __float2bfloat16(v - __bfloat162float(hi));
}

// ---------------- prep: split x into bf16 hi/lo ----------------
__global__ void __launch_bounds__(256) k_split_x(const float* __restrict__ x) {
    int t = blockIdx.x * 256 + threadIdx.x;
    float4 v = ((const float4*)x)[t];
    float vv[4] = {v.x, v.y, v.z, v.w};
    __nv_bfloat16 hi[4], lo[4];
    #pragma unroll
    for (int i = 0; i < 4; i++) split_bf16(vv[i], hi[i], lo[i]);
    __nv_bfloat162* ph = (__nv_bfloat162*)g_xhi;
    __nv_bfloat162* pl = (__nv_bfloat162*)g_xlo;
    ph[t*2]   = __nv_bfloat162(hi[0], hi[1]);
    ph[t*2+1] = __nv_bfloat162(hi[2], hi[3]);
    pl[t*2]   = __nv_bfloat162(lo[0], lo[1]);
    pl[t*2+1] = __nv_bfloat162(lo[2], lo[3]);
}

// ---------------- prep: transpose + split wq/wk -> W^T hi/lo ----------------
__global__ void __launch_bounds__(256) k_split_w(const float* __restrict__ wq,
                                                 const float* __restrict__ wk) {
    __shared__ float tile[32][33];
    int which = blockIdx.z;
    const float* src = which ? wk : wq;            // src[k][n]
    int k0 = blockIdx.y * 32, n0 = blockIdx.x * 32;
    int tx = threadIdx.x & 31, ty = threadIdx.x >> 5;
    #pragma unroll
    for (int i = 0; i < 4; i++)
        tile[ty + 8*i][tx] = src[(size_t)(k0 + ty + 8*i) * DM + n0 + tx];
    __syncthreads();
    size_t base = (size_t)which * DM * DM;
    #pragma unroll
    for (int i = 0; i < 4; i++) {
        float v = tile[tx][ty + 8*i];
        __nv_bfloat16 hi, lo;
        split_bf16(v, hi, lo);
        size_t idx = base + (size_t)(n0 + ty + 8*i) * DM + k0 + tx;
        g_wthi[idx] = hi;
        g_wtlo[idx] = lo;
    }
}

// ---------------- kernel A: fold wo into wv -> wvo (coalesced, warp-per-row) ------
// 8 warps/block, warp handles one din row; wo staged in smem; 128 blocks.
__global__ void __launch_bounds__(256) k_wvo(const float* __restrict__ wv,
                                             const float* __restrict__ wo,
                                             const float* __restrict__ bv) {
    __shared__ float wo_sm[DM];
    int tid = threadIdx.x, lane = tid & 31, wrp = tid >> 5;
    ((float4*)wo_sm)[tid] = ((const float4*)wo)[tid];
    __syncthreads();
    int din = blockIdx.x * 8 + wrp;
    const float4* row4 = (const float4*)(wv + (size_t)din * DM);
    const float4* wo4  = (const float4*)wo_sm;
    #pragma unroll
    for (int t = 0; t < 8; t++) {
        float4 xv = row4[lane + 32 * t];
        float4 wv4 = wo4[lane + 32 * t];
        float p = xv.x * wv4.x + xv.y * wv4.y + xv.z * wv4.z + xv.w * wv4.w;
        p += __shfl_xor_sync(0xffffffffu, p, 1);
        p += __shfl_xor_sync(0xffffffffu, p, 2);
        p += __shfl_xor_sync(0xffffffffu, p, 4);
        p += __shfl_xor_sync(0xffffffffu, p, 8);
        int h = 2 * t + (lane >> 4);
        if ((lane & 15) == 0) g_wvo[h * DM + din] = p;
    }
    // bvo: block 0, 16 threads, each one head (tiny)
    if (blockIdx.x == 0 && tid < NH) {
        float bb = 0.f;
        #pragma unroll
        for (int e = 0; e < HD; e++) bb += bv[tid * HD + e] * wo_sm[tid * HD + e];
        g_bvo[tid] = bb;
    }
}

// ---------------- kernel B: u = X @ wvo^T; 8 x-rows staged in smem, wvo in regs ----
__global__ void __launch_bounds__(512) k_u(const float* __restrict__ x) {
    __shared__ float xs[8 * DM];               // 32 KB
    int tid = threadIdx.x, lane = tid & 31, h = tid >> 5;   // warp = head
    int row0 = blockIdx.x * 8;                 // 256 blocks
    const float4* src = (const float4*)(x + (size_t)row0 * DM);
    #pragma unroll
    for (int t = 0; t < 4; t++)
        ((float4*)xs)[tid + t * 512] = src[tid + t * 512];
    float4 wr[8];
    const float4* wv4 = (const float4*)(g_wvo + h * DM);
    #pragma unroll
    for (int t = 0; t < 8; t++) wr[t] = wv4[lane + 32 * t];
    float bvo = g_bvo[h];
    __syncthreads();
    #pragma unroll
    for (int rr = 0; rr < 8; rr++) {
        const float4* xr4 = (const float4*)(xs + rr * DM);
        float acc = 0.f;
        #pragma unroll
        for (int t = 0; t < 8; t++) {
            float4 xv = xr4[lane + 32 * t];
            acc += xv.x * wr[t].x + xv.y * wr[t].y + xv.z * wr[t].z + xv.w * wr[t].w;
        }
        #pragma unroll
        for (int o = 16; o > 0; o >>= 1) acc += __shfl_xor_sync(0xffffffffu, acc, o);
        if (lane == 0) {
            int m = row0 + rr;
            int b = m >> 9, j = m & (NL - 1);
            g_u[(b * NH + h) * NL + j] = acc + bvo;
        }
    }
}

// ---------------- kernel C: Q/K projection via mma.sync -> split-bf16 q/k ----------
#define PITCH   40
#define T_BYTES (128 * PITCH * 2)
#define OA_HI   0
#define OA_LO   (T_BYTES)
#define OB_HI   (2 * T_BYTES)
#define OB_LO   (3 * T_BYTES)
#define BUF_B   (4 * T_BYTES)
#define HMMA_SMEM (2 * BUF_B)
__global__ void __launch_bounds__(256) k_proj_hmma(const float* __restrict__ bq,
                                                   const float* __restrict__ bk) {
    extern __shared__ char smem[];
    uint32_t sb = smem_u32(smem);
    int tid = threadIdx.x, lane = tid & 31, wid = tid >> 5;
    int which = blockIdx.z;
    const __nv_bfloat16* Bh = g_wthi + (size_t)which * DM * DM;
    const __nv_bfloat16* Bl = g_wtlo + (size_t)which * DM * DM;
    __nv_bfloat16* ohi = which ? g_khi : g_qhi;
    __nv_bfloat16* olo = which ? g_klo : g_qlo;
    const float* bvec = which ? bk : bq;
    const float oscale = which ? 1.0f : 0.125f;    // fold 1/sqrt(64) into q
    int m0 = blockIdx.y * 128, n0 = blockIdx.x * 128;
    int warp_m = wid & 1, warp_n = wid >> 1;
    int wm_base = warp_m * 64, wn_base = warp_n * 32;

    float acc[4][4][4];
    #pragma unroll
    for (int mi = 0; mi < 4; mi++)
        #pragma unroll
        for (int ni = 0; ni < 4; ni++)
            #pragma unroll
            for (int e = 0; e < 4; e++) acc[mi][ni][e] = 0.f;

    int l_row[2], l_c8[2];
    #pragma unroll
    for (int t = 0; t < 2; t++) { int f = tid + t * 256; l_row[t] = f >> 2; l_c8[t] = f & 3; }

    uint4 rah[2], ral[2], rbh[2], rbl[2];
    auto load_regs = [&](int c) {
        int k0 = c * 32;
        #pragma unroll
        for (int t = 0; t < 2; t++) {
            size_t ga = (size_t)(m0 + l_row[t]) * DM + k0 + l_c8[t] * 8;
            size_t gb = (size_t)(n0 + l_row[t]) * DM + k0 + l_c8[t] * 8;
            rah[t] = *(const uint4*)(g_xhi + ga);
            ral[t] = *(const uint4*)(g_xlo + ga);
            rbh[t] = *(const uint4*)(Bh + gb);
            rbl[t] = *(const uint4*)(Bl + gb);
        }
    };
    auto store_smem = [&](int buf) {
        char* base = smem + buf * BUF_B;
        #pragma unroll
        for (int t = 0; t < 2; t++) {
            uint32_t off = (uint32_t)(l_row[t] * (PITCH * 2) + l_c8[t] * 16);
            *(uint4*)(base + OA_HI + off) = rah[t];
            *(uint4*)(base + OA_LO + off) = ral[t];
            *(uint4*)(base + OB_HI + off) = rbh[t];
            *(uint4*)(base + OB_LO + off) = rbl[t];
        }
    };

    load_regs(0);
    store_smem(0);
    __syncthreads();

    int buf = 0;
    for (int c = 0; c < 32; c++) {
        if (c < 31) load_regs(c + 1);
        uint32_t bb = sb + buf * BUF_B;
        #pragma unroll
        for (int ks = 0; ks < 2; ks++) {
            uint32_t ah[4][4], al[4][4], bh[4][2], bl[4][2];
            #pragma unroll
            for (int mi = 0; mi < 4; mi++) {
                uint32_t ro = (uint32_t)((wm_base + mi * 16 + (lane & 15)) * (PITCH * 2)
                              + (lane >> 4) * 16 + ks * 32);
                ldsm_x4(ah[mi][0], ah[mi][1], ah[mi][2], ah[mi][3], bb + OA_HI + ro);
                ldsm_x4(al[mi][0], al[mi][1], al[mi][2], al[mi][3], bb + OA_LO + ro);
            }
            #pragma unroll
            for (int ni = 0; ni < 4; ni++) {
                uint32_t ro = (uint32_t)((wn_base + ni * 8 + (lane & 7)) * (PITCH * 2)
                              + ((lane >> 3) & 1) * 16 + ks * 32);
                ldsm_x2(bh[ni][0], bh[ni][1], bb + OB_HI + ro);
                ldsm_x2(bl[ni][0], bl[ni][1], bb + OB_LO + ro);
            }
            #pragma unroll
            for (int mi = 0; mi < 4; mi++)
                #pragma unroll
                for (int ni = 0; ni < 4; ni++) {
                    mma_bf16(acc[mi][ni], ah[mi], bh[ni]);
                    mma_bf16(acc[mi][ni], ah[mi], bl[ni]);
                    mma_bf16(acc[mi][ni], al[mi], bh[ni]);
                }
        }
        if (c < 31) {
            store_smem(buf ^ 1);
            __syncthreads();
            buf ^= 1;
        }
    }

    int groupID = lane >> 2, qc = (lane & 3) * 2;
    #pragma unroll
    for (int mi = 0; mi < 4; mi++) {
        #pragma unroll
        for (int half = 0; half < 2; half++) {
            int m = m0 + wm_base + mi * 16 + groupID + half * 8;
            int b = m >> 9, ii = m & (NL - 1);
            #pragma unroll
            for (int ni = 0; ni < 4; ni++) {
                int n = n0 + wn_base + ni * 8 + qc;
                int h = n >> 6, d = n & 63;
                float vx = (acc[mi][ni][half * 2 + 0] + bvec[n])     * oscale;
                float vy = (acc[mi][ni][half * 2 + 1] + bvec[n + 1]) * oscale;
                __nv_bfloat16 hx, lx, hy, ly;
                split_bf16(vx, hx, lx);
                split_bf16(vy, hy, ly);
                size_t o = ((size_t)(b * NH + h) * NL + ii) * HD + d;
                *(__nv_bfloat162*)(ohi + o) = __nv_bfloat162(hx, hy);
                *(__nv_bfloat162*)(olo + o) = __nv_bfloat162(lx, ly);
            }
        }
    }
}

// ---------------- kernel D: HMMA logits -> exp -> ew + rowsums ----------
// 128x128 i-tile x j-tile, 8 warps (2m x 4n), split-bf16 3-term mma.
#define QP 72                              // bf16 pitch (144 B rows, conflict-free)
#define AT_QHI 0
#define AT_QLO (128 * QP * 2)
#define AT_KHI (2 * 128 * QP * 2)
#define AT_KLO (3 * 128 * QP * 2)
#define ATTN_SMEM (4 * 128 * QP * 2)       // 73,728 B
__global__ void __launch_bounds__(256) k_attn(const float* __restrict__ bias,
                                              const int* __restrict__ mask) {
    extern __shared__ char smem[];
    __shared__ float rs_sm[4][128];
    uint32_t sb = smem_u32(smem);
    int tid = threadIdx.x, lane = tid & 31, wid = tid >> 5;
    int warp_m = wid & 1, warp_n = wid >> 1;
    int wm = warp_m * 64, wn = warp_n * 32;
    int b = blockIdx.z, h = blockIdx.y, i0 = blockIdx.x * 128;
    const __nv_bfloat16* qh = g_qhi + ((size_t)(b * NH + h) * NL + i0) * HD;
    const __nv_bfloat16* ql = g_qlo + ((size_t)(b * NH + h) * NL + i0) * HD;
    const __nv_bfloat16* kh = g_khi + (size_t)(b * NH + h) * NL * HD;
    const __nv_bfloat16* kl = g_klo + (size_t)(b * NH + h) * NL * HD;
    const float* urow = g_u + (size_t)(b * NH + h) * NL;

    // load q tile: 128 rows x 64 bf16 (128 B) -> pitch-144 smem
    #pragma unroll
    for (int t = 0; t < 4; t++) {
        int f = tid + t * 256;             // 1024 chunks
        int r = f >> 3, c = f & 7;
        *(uint4*)(smem + AT_QHI + r * (QP * 2) + c * 16) = *(const uint4*)(qh + r * HD + c * 8);
        *(uint4*)(smem + AT_QLO + r * (QP * 2) + c * 16) = *(const uint4*)(ql + r * HD + c * 8);
    }
    for (int idx = tid; idx < 512; idx += 256) ((float*)rs_sm)[idx] = 0.f;

    int groupID = lane >> 2, qc = (lane & 3) * 2;
    float rs8[8];
    #pragma unroll
    for (int i = 0; i < 8; i++) rs8[i] = 0.f;

    for (int jt = 0; jt < NL; jt += 128) {
        __syncthreads();
        #pragma unroll
        for (int t = 0; t < 4; t++) {
            int f = tid + t * 256;
            int r = f >> 3, c = f & 7;
            *(uint4*)(smem + AT_KHI + r * (QP * 2) + c * 16) =
                *(const uint4*)(kh + (size_t)(jt + r) * HD + c * 8);
            *(uint4*)(smem + AT_KLO + r * (QP * 2) + c * 16) =
                *(const uint4*)(kl + (size_t)(jt + r) * HD + c * 8);
        }
        __syncthreads();

        float acc[4][4][4];
        #pragma unroll
        for (int mi = 0; mi < 4; mi++)
            #pragma unroll
            for (int ni = 0; ni < 4; ni++)
                #pragma unroll
                for (int e = 0; e < 4; e++) acc[mi][ni][e] = 0.f;

        #pragma unroll
        for (int ks = 0; ks < 4; ks++) {
            uint32_t ah[4][4], al[4][4], bh[4][2], bl[4][2];
            #pragma unroll
            for (int mi = 0; mi < 4; mi++) {
                uint32_t ro = (uint32_t)((wm + mi * 16 + (lane & 15)) * (QP * 2)
                              + (lane >> 4) * 16 + ks * 32);
                ldsm_x4(ah[mi][0], ah[mi][1], ah[mi][2], ah[mi][3], sb + AT_QHI + ro);
                ldsm_x4(al[mi][0], al[mi][1], al[mi][2], al[mi][3], sb + AT_QLO + ro);
            }
            #pragma unroll
            for (int ni = 0; ni < 4; ni++) {
                uint32_t ro = (uint32_t)((wn + ni * 8 + (lane & 7)) * (QP * 2)
                              + ((lane >> 3) & 1) * 16 + ks * 32);
                ldsm_x2(bh[ni][0], bh[ni][1], sb + AT_KHI + ro);
                ldsm_x2(bl[ni][0], bl[ni][1], sb + AT_KLO + ro);
            }
            #pragma unroll
            for (int mi = 0; mi < 4; mi++)
                #pragma unroll
                for (int ni = 0; ni < 4; ni++) {
                    mma_bf16(acc[mi][ni], ah[mi], bh[ni]);
                    mma_bf16(acc[mi][ni], ah[mi], bl[ni]);
                    mma_bf16(acc[mi][ni], al[mi], bh[ni]);
                }
        }

        // epilogue: bias + mask + exp, fold u, accumulate row sums
        float2 uv2[4];
        #pragma unroll
        for (int ni = 0; ni < 4; ni++)
            uv2[ni] = *(const float2*)&urow[jt + wn + ni * 8 + qc];
        #pragma unroll
        for (int mi = 0; mi < 4; mi++) {
            #pragma unroll
            for (int half = 0; half < 2; half++) {
                int gi = i0 + wm + mi * 16 + groupID + half * 8;
                const float* brow = bias + ((size_t)(b * NH + h) * NL + gi) * NL + jt;
                const int*   mrow = mask + ((size_t)b * NL + gi) * NL + jt;
                float* wrow = g_w + ((size_t)(b * NH + h) * NL + gi) * NL + jt;
                float rloc = 0.f;
                #pragma unroll
                for (int ni = 0; ni < 4; ni++) {
                    int col = wn + ni * 8 + qc;
                    float2 bb = *(const float2*)&brow[col];
                    int2   mm = *(const int2*)&mrow[col];
                    float e0 = mm.x ? __expf(acc[mi][ni][half * 2 + 0] + bb.x) : 0.f;
                    float e1 = mm.y ? __expf(acc[mi][ni][half * 2 + 1] + bb.y) : 0.f;
                    rloc += e0 + e1;
                    *(float2*)&wrow[col] = make_float2(e0 * uv2[ni].x, e1 * uv2[ni].y);
                }
                rs8[mi * 2 + half] += rloc;
            }
        }
    }

    // reduce rs over quad lanes (cols), deposit per-warp_n partials, combine
    #pragma unroll
    for (int i = 0; i < 8; i++) {
        rs8[i] += __shfl_xor_sync(0xffffffffu, rs8[i], 1);
        rs8[i] += __shfl_xor_sync(0xffffffffu, rs8[i], 2);
    }
    if ((lane & 3) == 0) {
        #pragma unroll
        for (int mi = 0; mi < 4; mi++)
            #pragma unroll
            for (int half = 0; half < 2; half++)
                rs_sm[warp_n][wm + mi * 16 + groupID + half * 8] = rs8[mi * 2 + half];
    }
    __syncthreads();
    if (tid < 128) {
        float s = rs_sm[0][tid] + rs_sm[1][tid] + rs_sm[2][tid] + rs_sm[3][tid];
        g_irs[(size_t)(b * NH + h) * NL + i0 + tid] = 1.f / s;
    }
}

// ---------------- kernel E: s[j] = sum_h irs[h]*ew[h,i,j]; force = r @ s + bo ----
__global__ void __launch_bounds__(128) k_out(const float* __restrict__ r,
                                             const float* __restrict__ bo,
                                             float* __restrict__ out) {
    int bi = blockIdx.x;
    int b = bi >> 9, i = bi & (NL - 1);
    __shared__ float4 s4[NL / 4];
    __shared__ float irs_s[NH];
    __shared__ float red[3][4];
    int tid = threadIdx.x;
    if (tid < NH) irs_s[tid] = g_irs[(size_t)(b * NH + tid) * NL + i];
    __syncthreads();

    const float* wbase = g_w + ((size_t)(b * NH) * NL + i) * NL;
    float4 a = make_float4(0.f, 0.f, 0.f, 0.f);
    #pragma unroll
    for (int h = 0; h < NH; h++) {
        float4 wv4 = ((const float4*)(wbase + (size_t)h * NL * NL))[tid];
        float ir = irs_s[h];
        a.x += ir * wv4.x; a.y += ir * wv4.y;
        a.z += ir * wv4.z; a.w += ir * wv4.w;
    }
    s4[tid] = a;
    __syncthreads();

    float p[3];
    #pragma unroll
    for (int c = 0; c < 3; c++) {
        const float4* rr = (const float4*)(r + ((size_t)(b * 3 + c) * NL + i) * NL);
        float4 rv = rr[tid];
        float4 sv = s4[tid];
        p[c] = rv.x * sv.x + rv.y * sv.y + rv.z * sv.z + rv.w * sv.w;
    }
    int lane = tid & 31, wrp = tid >> 5;
    #pragma unroll
    for (int c = 0; c < 3; c++) {
        #pragma unroll
        for (int o = 16; o > 0; o >>= 1)
            p[c] += __shfl_xor_sync(0xffffffffu, p[c], o);
        if (lane == 0) red[c][wrp] = p[c];
    }
    __syncthreads();
    if (tid < 3)
        out[bi * 3 + tid] = red[tid][0] + red[tid][1] + red[tid][2] + red[tid][3] + bo[0];
}

// ---------------- launch ----------------
extern "C" void kernel_launch(void* const* d_in, const int* in_sizes, int n_in,
                              void* d_out, int out_size) {
    const float* x    = (const float*)d_in[0];
    const float* r    = (const float*)d_in[1];
    const float* bias = (const float*)d_in[2];
    const int*   mask = (const int*)d_in[3];
    const float* wq   = (const float*)d_in[4];
    const float* bq   = (const float*)d_in[5];
    const float* wk   = (const float*)d_in[6];
    const float* bk   = (const float*)d_in[7];
    const float* wv   = (const float*)d_in[8];
    const float* bv   = (const float*)d_in[9];
    const float* wo   = (const float*)d_in[10];
    const float* bo   = (const float*)d_in[11];
    float* out = (float*)d_out;

    cudaFuncSetAttribute(k_attn, cudaFuncAttributeMaxDynamicSharedMemorySize, ATTN_SMEM);
    cudaFuncSetAttribute(k_proj_hmma, cudaFuncAttributeMaxDynamicSharedMemorySize, HMMA_SMEM);

    k_split_x<<<BSZ * NL * DM / 1024, 256>>>(x);
    k_split_w<<<dim3(DM / 32, DM / 32, 2), 256>>>(wq, wk);
    k_wvo<<<DM / 8, 256>>>(wv, wo, bv);
    k_u<<<BSZ * NL / 8, 512>>>(x);
    k_proj_hmma<<<dim3(DM / 128, (BSZ * NL) / 128, 2), 256, HMMA_SMEM>>>(bq, bk);
    k_attn<<<dim3(NL / 128, NH, BSZ), 256, ATTN_SMEM>>>(bias, mask);
    k_out<<<BSZ * NL, 128>>>(r, bo, out);
}